// round 3
// baseline (speedup 1.0000x reference)
#include <cuda_runtime.h>
#include <cuda_bf16.h>
#include <math.h>

#define N_NODES 10000
#define N_EDGES 640000
#define D 128

// ---------------- scratch (no allocations allowed) ----------------
__device__ int   g_deg[N_NODES];
__device__ int   g_cursor[N_NODES];
__device__ int   g_ptr[N_NODES + 1];
__device__ int   g_csr_src[N_EDGES];
__device__ float g_agg[N_NODES * D];
__device__ float g_h1[N_NODES * D];

// ---------------- CSR build ----------------
__global__ void zero_counts_kernel(int n) {
    int i = blockIdx.x * blockDim.x + threadIdx.x;
    if (i < n) { g_deg[i] = 0; g_cursor[i] = 0; }
}

__global__ void count_edges_kernel(const int* __restrict__ ei, int E, int n) {
    int e = blockIdx.x * blockDim.x + threadIdx.x;
    if (e < E) {
        int d = ei[E + e];   // dst row
        if (d >= 0 && d < n) atomicAdd(&g_deg[d], 1);
    }
}

// single-block scan over g_deg -> g_ptr (g_ptr[0]=0, g_ptr[i+1]=sum deg[0..i])
__global__ void scan_kernel(int n) {
    __shared__ int sh[1024];
    __shared__ int sh_carry;
    if (threadIdx.x == 0) { g_ptr[0] = 0; sh_carry = 0; }
    __syncthreads();
    for (int base = 0; base < n; base += 1024) {
        int i = base + (int)threadIdx.x;
        int v = (i < n) ? g_deg[i] : 0;
        sh[threadIdx.x] = v;
        __syncthreads();
        #pragma unroll
        for (int off = 1; off < 1024; off <<= 1) {
            int t = (threadIdx.x >= (unsigned)off) ? sh[threadIdx.x - off] : 0;
            __syncthreads();
            sh[threadIdx.x] += t;
            __syncthreads();
        }
        int carry = sh_carry;
        if (i < n) g_ptr[i + 1] = carry + sh[threadIdx.x];
        __syncthreads();
        if (threadIdx.x == 0) sh_carry = carry + sh[1023];
        __syncthreads();
    }
}

__global__ void fill_csr_kernel(const int* __restrict__ ei, int E, int n) {
    int e = blockIdx.x * blockDim.x + threadIdx.x;
    if (e < E) {
        int s = ei[e];       // src row
        int d = ei[E + e];   // dst row
        if (s >= 0 && s < n && d >= 0 && d < n) {
            int p = g_ptr[d] + atomicAdd(&g_cursor[d], 1);
            g_csr_src[p] = s;
        }
    }
}

// ---------------- aggregation: warp-per-node mean of gathered rows ----------------
// use_h1: read rows from g_h1 instead of X param. Output always -> g_agg.
__global__ void aggregate_kernel(const float* __restrict__ Xin, bool use_h1, int n) {
    const float* __restrict__ X = use_h1 ? (const float*)g_h1 : Xin;
    int warp = (blockIdx.x * blockDim.x + threadIdx.x) >> 5;
    int lane = threadIdx.x & 31;
    if (warp >= n) return;
    int s = g_ptr[warp];
    int e = g_ptr[warp + 1];

    float ax = 0.f, ay = 0.f, az = 0.f, aw = 0.f;
    int i = s;
    for (; i + 4 <= e; i += 4) {
        int j0 = g_csr_src[i + 0];
        int j1 = g_csr_src[i + 1];
        int j2 = g_csr_src[i + 2];
        int j3 = g_csr_src[i + 3];
        float4 v0 = *(const float4*)(X + (long long)j0 * D + lane * 4);
        float4 v1 = *(const float4*)(X + (long long)j1 * D + lane * 4);
        float4 v2 = *(const float4*)(X + (long long)j2 * D + lane * 4);
        float4 v3 = *(const float4*)(X + (long long)j3 * D + lane * 4);
        ax += v0.x + v1.x + v2.x + v3.x;
        ay += v0.y + v1.y + v2.y + v3.y;
        az += v0.z + v1.z + v2.z + v3.z;
        aw += v0.w + v1.w + v2.w + v3.w;
    }
    for (; i < e; i++) {
        int j = g_csr_src[i];
        float4 v = *(const float4*)(X + (long long)j * D + lane * 4);
        ax += v.x; ay += v.y; az += v.z; aw += v.w;
    }
    int deg = e - s;
    float inv = 1.0f / (float)(deg > 0 ? deg : 1);
    float4 o; o.x = ax * inv; o.y = ay * inv; o.z = az * inv; o.w = aw * inv;
    *(float4*)(g_agg + (long long)warp * D + lane * 4) = o;
}

// ---------------- fused GEMM: out = elu(g_agg@Wl + X@Wr + b) ----------------
// use_h1_in: X = g_h1 (else Xin param). write_h1: out = g_h1 (else Out param).
// block: 256 threads, tile 64 rows x 128 cols
__global__ void gemm_bias_elu_kernel(const float* __restrict__ Xin, bool use_h1_in,
                                     const float* __restrict__ Wl,  // [128,128]
                                     const float* __restrict__ Wr,  // [128,128]
                                     const float* __restrict__ bias,// [128]
                                     float* __restrict__ Out, bool write_h1,
                                     int n)
{
    const float* __restrict__ X   = use_h1_in ? (const float*)g_h1 : Xin;
    float* __restrict__ out       = write_h1  ? (float*)g_h1 : Out;
    const float* __restrict__ A   = (const float*)g_agg;

    __shared__ float As[64 * 32];
    __shared__ float Bs[32 * 128];
    int tid = threadIdx.x;
    int tx = tid & 31;   // col group: cols tx*4 .. tx*4+3
    int ty = tid >> 5;   // 0..7: rows ty + 8*r
    int row0 = blockIdx.x * 64;

    float acc[8][4];
    #pragma unroll
    for (int r = 0; r < 8; r++)
        #pragma unroll
        for (int c = 0; c < 4; c++) acc[r][c] = 0.f;

    #pragma unroll
    for (int phase = 0; phase < 2; phase++) {
        const float* Ap = phase ? X : A;
        const float* Wp = phase ? Wr : Wl;
        for (int k0 = 0; k0 < 128; k0 += 32) {
            // A tile: 64x32 = 512 float4, 2 per thread
            #pragma unroll
            for (int l = 0; l < 2; l++) {
                int idx = tid + l * 256;       // 0..511
                int r   = idx >> 3;            // row in tile
                int c4  = idx & 7;             // float4 within 32-float chunk
                float4 v = make_float4(0.f, 0.f, 0.f, 0.f);
                int gr = row0 + r;
                if (gr < n) v = *(const float4*)(Ap + (long long)gr * D + k0 + c4 * 4);
                *(float4*)(As + r * 32 + c4 * 4) = v;
            }
            // W tile: 32x128 = 1024 float4, 4 per thread
            #pragma unroll
            for (int l = 0; l < 4; l++) {
                int idx = tid + l * 256;       // 0..1023
                int r   = idx >> 5;            // k row
                int c4  = idx & 31;
                *(float4*)(Bs + r * 128 + c4 * 4) =
                    *(const float4*)(Wp + (long long)(k0 + r) * D + c4 * 4);
            }
            __syncthreads();
            #pragma unroll
            for (int kk = 0; kk < 32; kk++) {
                float4 bv = *(const float4*)(Bs + kk * 128 + tx * 4);
                #pragma unroll
                for (int r = 0; r < 8; r++) {
                    float a = As[(ty + r * 8) * 32 + kk];  // warp-broadcast
                    acc[r][0] += a * bv.x;
                    acc[r][1] += a * bv.y;
                    acc[r][2] += a * bv.z;
                    acc[r][3] += a * bv.w;
                }
            }
            __syncthreads();
        }
    }

    float4 bv = *(const float4*)(bias + tx * 4);
    #pragma unroll
    for (int r = 0; r < 8; r++) {
        int gr = row0 + ty + r * 8;
        if (gr < n) {
            float4 o;
            o.x = acc[r][0] + bv.x;
            o.y = acc[r][1] + bv.y;
            o.z = acc[r][2] + bv.z;
            o.w = acc[r][3] + bv.w;
            o.x = o.x > 0.f ? o.x : expm1f(o.x);
            o.y = o.y > 0.f ? o.y : expm1f(o.y);
            o.z = o.z > 0.f ? o.z : expm1f(o.z);
            o.w = o.w > 0.f ? o.w : expm1f(o.w);
            *(float4*)(out + (long long)gr * D + tx * 4) = o;
        }
    }
}

// ---------------- launch ----------------
extern "C" void kernel_launch(void* const* d_in, const int* in_sizes, int n_in,
                              void* d_out, int out_size) {
    const float* x   = (const float*)d_in[0];
    const int*   ei  = (const int*)d_in[1];      // int32 edge_index [2, E]
    const float* Wl0 = (const float*)d_in[2];
    const float* b0  = (const float*)d_in[3];
    const float* Wr0 = (const float*)d_in[4];
    const float* Wl1 = (const float*)d_in[5];
    const float* b1  = (const float*)d_in[6];
    const float* Wr1 = (const float*)d_in[7];
    float*       out = (float*)d_out;

    const int N = in_sizes[0] / D;          // 10000
    const int E = in_sizes[1] / 2;          // 640000

    // CSR build (rebuilt every launch; deterministic counts, cursor-ordered fill)
    zero_counts_kernel<<<(N + 255) / 256, 256>>>(N);
    count_edges_kernel<<<(E + 255) / 256, 256>>>(ei, E, N);
    scan_kernel<<<1, 1024>>>(N);
    fill_csr_kernel<<<(E + 255) / 256, 256>>>(ei, E, N);

    const int aggBlocks  = (N * 32 + 255) / 256;   // warp per node
    const int gemmBlocks = (N + 63) / 64;

    // layer 0: agg(x) -> gemm -> g_h1
    aggregate_kernel<<<aggBlocks, 256>>>(x, false, N);
    gemm_bias_elu_kernel<<<gemmBlocks, 256>>>(x, false, Wl0, Wr0, b0, nullptr, true, N);
    // layer 1: agg(g_h1) -> gemm -> d_out
    aggregate_kernel<<<aggBlocks, 256>>>(nullptr, true, N);
    gemm_bias_elu_kernel<<<gemmBlocks, 256>>>(nullptr, true, Wl1, Wr1, b1, out, false, N);
}

// round 5
// speedup vs baseline: 1.2671x; 1.2671x over previous
#include <cuda_runtime.h>
#include <cuda_bf16.h>
#include <math.h>

#define N_NODES 10000
#define N_EDGES 640000
#define D 128
#define CAP 256          // per-node bucket capacity (max deg ~100 for this dist)
#define OVF_MAX 8192

// ---------------- scratch (no allocations allowed) ----------------
__device__ int   g_cnt[N_NODES];
__device__ int   g_bucket[N_NODES * CAP];
__device__ int   g_ovf_cnt;
__device__ int   g_ovf[OVF_MAX * 2];     // (src,dst) pairs that overflowed
__device__ float g_agg[N_NODES * D];
__device__ float g_h1[N_NODES * D];

// ---------------- single-pass bucket scatter ----------------
__global__ void zero_kernel(int n) {
    int i = blockIdx.x * blockDim.x + threadIdx.x;
    if (i < n) g_cnt[i] = 0;
    if (i == 0) g_ovf_cnt = 0;
}

__global__ void scatter_kernel(const int* __restrict__ ei, int E, int n) {
    int e = blockIdx.x * blockDim.x + threadIdx.x;
    if (e < E) {
        int s = ei[e];       // src row
        int d = ei[E + e];   // dst row
        if (s >= 0 && s < n && d >= 0 && d < n) {
            int p = atomicAdd(&g_cnt[d], 1);
            if (p < CAP) {
                g_bucket[d * CAP + p] = s;
            } else {
                int q = atomicAdd(&g_ovf_cnt, 1);
                if (q < OVF_MAX) { g_ovf[2 * q] = s; g_ovf[2 * q + 1] = d; }
            }
        }
    }
}

// ---------------- aggregation: warp-per-node mean of gathered rows ----------------
// use_h1: read rows from g_h1 instead of X param. Output always -> g_agg.
__global__ void aggregate_kernel(const float* __restrict__ Xin, bool use_h1, int n) {
    const float* __restrict__ X = use_h1 ? (const float*)g_h1 : Xin;
    int warp = (blockIdx.x * blockDim.x + threadIdx.x) >> 5;
    int lane = threadIdx.x & 31;
    if (warp >= n) return;

    int cnt = g_cnt[warp];
    int e = cnt < CAP ? cnt : CAP;
    const int* __restrict__ bk = g_bucket + warp * CAP;

    float ax = 0.f, ay = 0.f, az = 0.f, aw = 0.f;
    int i = 0;
    for (; i + 8 <= e; i += 8) {
        int j0 = bk[i + 0]; int j1 = bk[i + 1];
        int j2 = bk[i + 2]; int j3 = bk[i + 3];
        int j4 = bk[i + 4]; int j5 = bk[i + 5];
        int j6 = bk[i + 6]; int j7 = bk[i + 7];
        float4 v0 = *(const float4*)(X + (long long)j0 * D + lane * 4);
        float4 v1 = *(const float4*)(X + (long long)j1 * D + lane * 4);
        float4 v2 = *(const float4*)(X + (long long)j2 * D + lane * 4);
        float4 v3 = *(const float4*)(X + (long long)j3 * D + lane * 4);
        float4 v4 = *(const float4*)(X + (long long)j4 * D + lane * 4);
        float4 v5 = *(const float4*)(X + (long long)j5 * D + lane * 4);
        float4 v6 = *(const float4*)(X + (long long)j6 * D + lane * 4);
        float4 v7 = *(const float4*)(X + (long long)j7 * D + lane * 4);
        ax += (v0.x + v1.x) + (v2.x + v3.x) + ((v4.x + v5.x) + (v6.x + v7.x));
        ay += (v0.y + v1.y) + (v2.y + v3.y) + ((v4.y + v5.y) + (v6.y + v7.y));
        az += (v0.z + v1.z) + (v2.z + v3.z) + ((v4.z + v5.z) + (v6.z + v7.z));
        aw += (v0.w + v1.w) + (v2.w + v3.w) + ((v4.w + v5.w) + (v6.w + v7.w));
    }
    for (; i < e; i++) {
        int j = bk[i];
        float4 v = *(const float4*)(X + (long long)j * D + lane * 4);
        ax += v.x; ay += v.y; az += v.z; aw += v.w;
    }

    // overflow edges (expected 0): scan tiny global list for ones targeting us
    int novf = g_ovf_cnt;
    if (novf > 0) {
        if (novf > OVF_MAX) novf = OVF_MAX;
        for (int q = 0; q < novf; q++) {
            if (g_ovf[2 * q + 1] == warp) {
                int j = g_ovf[2 * q];
                float4 v = *(const float4*)(X + (long long)j * D + lane * 4);
                ax += v.x; ay += v.y; az += v.z; aw += v.w;
            }
        }
    }

    float inv = 1.0f / (float)(cnt > 0 ? cnt : 1);
    float4 o; o.x = ax * inv; o.y = ay * inv; o.z = az * inv; o.w = aw * inv;
    *(float4*)(g_agg + (long long)warp * D + lane * 4) = o;
}

// ---------------- fused GEMM: out = elu(g_agg@Wl + X@Wr + b) ----------------
// use_h1_in: X = g_h1 (else Xin param). write_h1: out = g_h1 (else Out param).
// block: 256 threads, tile 64 rows x 128 cols
__global__ void gemm_bias_elu_kernel(const float* __restrict__ Xin, bool use_h1_in,
                                     const float* __restrict__ Wl,  // [128,128]
                                     const float* __restrict__ Wr,  // [128,128]
                                     const float* __restrict__ bias,// [128]
                                     float* __restrict__ Out, bool write_h1,
                                     int n)
{
    const float* __restrict__ X   = use_h1_in ? (const float*)g_h1 : Xin;
    float* __restrict__ out       = write_h1  ? (float*)g_h1 : Out;
    const float* __restrict__ A   = (const float*)g_agg;

    __shared__ float As[64 * 32];
    __shared__ float Bs[32 * 128];
    int tid = threadIdx.x;
    int tx = tid & 31;   // col group: cols tx*4 .. tx*4+3
    int ty = tid >> 5;   // 0..7: rows ty + 8*r
    int row0 = blockIdx.x * 64;

    float acc[8][4];
    #pragma unroll
    for (int r = 0; r < 8; r++)
        #pragma unroll
        for (int c = 0; c < 4; c++) acc[r][c] = 0.f;

    #pragma unroll
    for (int phase = 0; phase < 2; phase++) {
        const float* Ap = phase ? X : A;
        const float* Wp = phase ? Wr : Wl;
        #pragma unroll
        for (int k0 = 0; k0 < 128; k0 += 32) {
            // A tile: 64x32 = 512 float4, 2 per thread
            #pragma unroll
            for (int l = 0; l < 2; l++) {
                int idx = tid + l * 256;       // 0..511
                int r   = idx >> 3;            // row in tile
                int c4  = idx & 7;             // float4 within 32-float chunk
                float4 v = make_float4(0.f, 0.f, 0.f, 0.f);
                int gr = row0 + r;
                if (gr < n) v = *(const float4*)(Ap + (long long)gr * D + k0 + c4 * 4);
                *(float4*)(As + r * 32 + c4 * 4) = v;
            }
            // W tile: 32x128 = 1024 float4, 4 per thread
            #pragma unroll
            for (int l = 0; l < 4; l++) {
                int idx = tid + l * 256;       // 0..1023
                int r   = idx >> 5;            // k row
                int c4  = idx & 31;
                *(float4*)(Bs + r * 128 + c4 * 4) =
                    *(const float4*)(Wp + (long long)(k0 + r) * D + c4 * 4);
            }
            __syncthreads();
            #pragma unroll
            for (int kk = 0; kk < 32; kk++) {
                float4 bv = *(const float4*)(Bs + kk * 128 + tx * 4);
                #pragma unroll
                for (int r = 0; r < 8; r++) {
                    float a = As[(ty + r * 8) * 32 + kk];  // warp-broadcast
                    acc[r][0] += a * bv.x;
                    acc[r][1] += a * bv.y;
                    acc[r][2] += a * bv.z;
                    acc[r][3] += a * bv.w;
                }
            }
            __syncthreads();
        }
    }

    float4 bv = *(const float4*)(bias + tx * 4);
    #pragma unroll
    for (int r = 0; r < 8; r++) {
        int gr = row0 + ty + r * 8;
        if (gr < n) {
            float4 o;
            o.x = acc[r][0] + bv.x;
            o.y = acc[r][1] + bv.y;
            o.z = acc[r][2] + bv.z;
            o.w = acc[r][3] + bv.w;
            o.x = o.x > 0.f ? o.x : (__expf(o.x) - 1.0f);
            o.y = o.y > 0.f ? o.y : (__expf(o.y) - 1.0f);
            o.z = o.z > 0.f ? o.z : (__expf(o.z) - 1.0f);
            o.w = o.w > 0.f ? o.w : (__expf(o.w) - 1.0f);
            *(float4*)(out + (long long)gr * D + tx * 4) = o;
        }
    }
}

// ---------------- launch ----------------
extern "C" void kernel_launch(void* const* d_in, const int* in_sizes, int n_in,
                              void* d_out, int out_size) {
    const float* x   = (const float*)d_in[0];
    const int*   ei  = (const int*)d_in[1];      // int32 edge_index [2, E]
    const float* Wl0 = (const float*)d_in[2];
    const float* b0  = (const float*)d_in[3];
    const float* Wr0 = (const float*)d_in[4];
    const float* Wl1 = (const float*)d_in[5];
    const float* b1  = (const float*)d_in[6];
    const float* Wr1 = (const float*)d_in[7];
    float*       out = (float*)d_out;

    const int N = in_sizes[0] / D;          // 10000
    const int E = in_sizes[1] / 2;          // 640000

    // single-pass bucket build (rebuilt every launch)
    zero_kernel<<<(N + 255) / 256, 256>>>(N);
    scatter_kernel<<<(E + 255) / 256, 256>>>(ei, E, N);

    const int aggBlocks  = (N * 32 + 255) / 256;   // warp per node
    const int gemmBlocks = (N + 63) / 64;

    // layer 0: agg(x) -> gemm -> g_h1
    aggregate_kernel<<<aggBlocks, 256>>>(x, false, N);
    gemm_bias_elu_kernel<<<gemmBlocks, 256>>>(x, false, Wl0, Wr0, b0, nullptr, true, N);
    // layer 1: agg(g_h1) -> gemm -> d_out
    aggregate_kernel<<<aggBlocks, 256>>>(nullptr, true, N);
    gemm_bias_elu_kernel<<<gemmBlocks, 256>>>(nullptr, true, Wl1, Wr1, b1, out, false, N);
}

// round 7
// speedup vs baseline: 1.3521x; 1.0671x over previous
#include <cuda_runtime.h>
#include <cuda_bf16.h>
#include <math.h>

#define N_NODES 10000
#define N_EDGES 640000
#define D 128
#define CAP 256          // per-node bucket capacity (max deg ~100 for this dist)
#define OVF_MAX 8192
#define TILE 32          // rows per fused block

// ---------------- scratch (no allocations allowed) ----------------
__device__ int   g_cnt[N_NODES];
__device__ int   g_bucket[N_NODES * CAP];
__device__ int   g_ovf_cnt;
__device__ int   g_ovf[OVF_MAX * 2];     // (src,dst) pairs that overflowed
__device__ float g_h1[N_NODES * D];

// ---------------- single-pass bucket scatter ----------------
__global__ void zero_kernel(int n) {
    int i = blockIdx.x * blockDim.x + threadIdx.x;
    if (i < n) g_cnt[i] = 0;
    if (i == 0) g_ovf_cnt = 0;
}

__global__ void scatter_kernel(const int* __restrict__ ei, int E, int n) {
    int e = blockIdx.x * blockDim.x + threadIdx.x;
    if (e < E) {
        int s = ei[e];       // src row
        int d = ei[E + e];   // dst row
        if (s >= 0 && s < n && d >= 0 && d < n) {
            int p = atomicAdd(&g_cnt[d], 1);
            if (p < CAP) {
                g_bucket[d * CAP + p] = s;
            } else {
                int q = atomicAdd(&g_ovf_cnt, 1);
                if (q < OVF_MAX) { g_ovf[2 * q] = s; g_ovf[2 * q + 1] = d; }
            }
        }
    }
}

// ---------------- fused layer: out = elu(mean_nbr(X)@Wl + X@Wr + b) ----------------
// Phase A: warp-per-node gather+mean into smem As, stage X rows into Xs.
// Phase B: 32x128 GEMM over K=256 ([As | Xs] @ [Wl ; Wr]) + bias + ELU.
__global__ void fused_layer_kernel(const float* __restrict__ Xin, bool use_h1_in,
                                   const float* __restrict__ Wl,   // [128,128]
                                   const float* __restrict__ Wr,   // [128,128]
                                   const float* __restrict__ bias, // [128]
                                   float* __restrict__ Out, bool write_h1,
                                   int n)
{
    const float* __restrict__ X = use_h1_in ? (const float*)g_h1 : Xin;
    float* __restrict__ out     = write_h1  ? (float*)g_h1 : Out;

    __shared__ float As[TILE * D];   // 16 KB  aggregated means
    __shared__ float Xs[TILE * D];   // 16 KB  self features
    __shared__ float Bs[32 * D];     // 16 KB  W k-chunk

    int tid  = threadIdx.x;
    int warp = tid >> 5;             // 0..7
    int lane = tid & 31;
    int row0 = blockIdx.x * TILE;

    // ---------- Phase A: gather (4 nodes per warp) ----------
    #pragma unroll
    for (int t = 0; t < 4; t++) {
        int rt   = (warp << 2) + t;      // row in tile 0..31
        int node = row0 + rt;
        if (node < n) {
            int cnt = g_cnt[node];
            int e = cnt < CAP ? cnt : CAP;
            const int* __restrict__ bk = g_bucket + node * CAP;

            float ax = 0.f, ay = 0.f, az = 0.f, aw = 0.f;
            int i = 0;
            for (; i + 8 <= e; i += 8) {
                int j0 = bk[i + 0]; int j1 = bk[i + 1];
                int j2 = bk[i + 2]; int j3 = bk[i + 3];
                int j4 = bk[i + 4]; int j5 = bk[i + 5];
                int j6 = bk[i + 6]; int j7 = bk[i + 7];
                float4 v0 = *(const float4*)(X + (long long)j0 * D + lane * 4);
                float4 v1 = *(const float4*)(X + (long long)j1 * D + lane * 4);
                float4 v2 = *(const float4*)(X + (long long)j2 * D + lane * 4);
                float4 v3 = *(const float4*)(X + (long long)j3 * D + lane * 4);
                float4 v4 = *(const float4*)(X + (long long)j4 * D + lane * 4);
                float4 v5 = *(const float4*)(X + (long long)j5 * D + lane * 4);
                float4 v6 = *(const float4*)(X + (long long)j6 * D + lane * 4);
                float4 v7 = *(const float4*)(X + (long long)j7 * D + lane * 4);
                ax += (v0.x + v1.x) + (v2.x + v3.x) + ((v4.x + v5.x) + (v6.x + v7.x));
                ay += (v0.y + v1.y) + (v2.y + v3.y) + ((v4.y + v5.y) + (v6.y + v7.y));
                az += (v0.z + v1.z) + (v2.z + v3.z) + ((v4.z + v5.z) + (v6.z + v7.z));
                aw += (v0.w + v1.w) + (v2.w + v3.w) + ((v4.w + v5.w) + (v6.w + v7.w));
            }
            for (; i < e; i++) {
                int j = bk[i];
                float4 v = *(const float4*)(X + (long long)j * D + lane * 4);
                ax += v.x; ay += v.y; az += v.z; aw += v.w;
            }
            // overflow edges (expected none)
            int novf = g_ovf_cnt;
            if (novf > 0) {
                if (novf > OVF_MAX) novf = OVF_MAX;
                for (int q = 0; q < novf; q++) {
                    if (g_ovf[2 * q + 1] == node) {
                        int j = g_ovf[2 * q];
                        float4 v = *(const float4*)(X + (long long)j * D + lane * 4);
                        ax += v.x; ay += v.y; az += v.z; aw += v.w;
                    }
                }
            }
            float inv = 1.0f / (float)(cnt > 0 ? cnt : 1);
            float4 m; m.x = ax * inv; m.y = ay * inv; m.z = az * inv; m.w = aw * inv;
            *(float4*)(As + rt * D + lane * 4) = m;
            *(float4*)(Xs + rt * D + lane * 4) =
                *(const float4*)(X + (long long)node * D + lane * 4);
        } else {
            float4 z = make_float4(0.f, 0.f, 0.f, 0.f);
            *(float4*)(As + rt * D + lane * 4) = z;
            *(float4*)(Xs + rt * D + lane * 4) = z;
        }
    }
    __syncthreads();

    // ---------- Phase B: GEMM 32x128, K = 2*128 ----------
    int tx = tid & 31;   // col group: cols tx*4 .. tx*4+3
    int ty = tid >> 5;   // rows ty + 8*r, r in 0..3

    float acc[4][4];
    #pragma unroll
    for (int r = 0; r < 4; r++)
        #pragma unroll
        for (int c = 0; c < 4; c++) acc[r][c] = 0.f;

    #pragma unroll
    for (int phase = 0; phase < 2; phase++) {
        const float* __restrict__ Ap = phase ? Xs : As;   // smem
        const float* __restrict__ Wp = phase ? Wr : Wl;   // gmem (L2)
        #pragma unroll
        for (int k0 = 0; k0 < D; k0 += 32) {
            // W chunk: 32x128 floats = 1024 float4, 4 per thread
            #pragma unroll
            for (int l = 0; l < 4; l++) {
                int idx = tid + l * 256;        // 0..1023
                int r   = idx >> 5;             // k row 0..31
                int c4  = idx & 31;
                *(float4*)(Bs + r * D + c4 * 4) =
                    *(const float4*)(Wp + (long long)(k0 + r) * D + c4 * 4);
            }
            __syncthreads();
            #pragma unroll
            for (int kk = 0; kk < 32; kk++) {
                float4 bv = *(const float4*)(Bs + kk * D + tx * 4);
                #pragma unroll
                for (int r = 0; r < 4; r++) {
                    float a = Ap[(ty + r * 8) * D + k0 + kk];  // warp-broadcast
                    acc[r][0] += a * bv.x;
                    acc[r][1] += a * bv.y;
                    acc[r][2] += a * bv.z;
                    acc[r][3] += a * bv.w;
                }
            }
            __syncthreads();
        }
    }

    // ---------- epilogue ----------
    float4 bv = *(const float4*)(bias + tx * 4);
    #pragma unroll
    for (int r = 0; r < 4; r++) {
        int gr = row0 + ty + r * 8;
        if (gr < n) {
            float4 o;
            o.x = acc[r][0] + bv.x;
            o.y = acc[r][1] + bv.y;
            o.z = acc[r][2] + bv.z;
            o.w = acc[r][3] + bv.w;
            o.x = o.x > 0.f ? o.x : (__expf(o.x) - 1.0f);
            o.y = o.y > 0.f ? o.y : (__expf(o.y) - 1.0f);
            o.z = o.z > 0.f ? o.z : (__expf(o.z) - 1.0f);
            o.w = o.w > 0.f ? o.w : (__expf(o.w) - 1.0f);
            *(float4*)(out + (long long)gr * D + tx * 4) = o;
        }
    }
}

// ---------------- launch ----------------
extern "C" void kernel_launch(void* const* d_in, const int* in_sizes, int n_in,
                              void* d_out, int out_size) {
    const float* x   = (const float*)d_in[0];
    const int*   ei  = (const int*)d_in[1];      // int32 edge_index [2, E]
    const float* Wl0 = (const float*)d_in[2];
    const float* b0  = (const float*)d_in[3];
    const float* Wr0 = (const float*)d_in[4];
    const float* Wl1 = (const float*)d_in[5];
    const float* b1  = (const float*)d_in[6];
    const float* Wr1 = (const float*)d_in[7];
    float*       out = (float*)d_out;

    const int N = in_sizes[0] / D;          // 10000
    const int E = in_sizes[1] / 2;          // 640000

    // single-pass bucket build (rebuilt every launch)
    zero_kernel<<<(N + 255) / 256, 256>>>(N);
    scatter_kernel<<<(E + 255) / 256, 256>>>(ei, E, N);

    const int blocks = (N + TILE - 1) / TILE;   // 313

    // layer 0: fused agg+gemm -> g_h1
    fused_layer_kernel<<<blocks, 256>>>(x, false, Wl0, Wr0, b0, nullptr, true, N);
    // layer 1: fused agg+gemm -> d_out
    fused_layer_kernel<<<blocks, 256>>>(nullptr, true, Wl1, Wr1, b1, out, false, N);
}

// round 8
// speedup vs baseline: 1.4264x; 1.0550x over previous
#include <cuda_runtime.h>
#include <cuda_bf16.h>
#include <math.h>

#define N_NODES 10000
#define N_EDGES 640000
#define D 128
#define CAP 256          // per-node bucket capacity (max deg ~100 for this dist)
#define OVF_MAX 8192
#define TILE 16          // rows per fused block
#define NTHREADS 128

// ---------------- scratch (no allocations allowed) ----------------
__device__ int   g_cnt[N_NODES];
__device__ int   g_bucket[N_NODES * CAP];
__device__ int   g_ovf_cnt;
__device__ int   g_ovf[OVF_MAX * 2];     // (src,dst) pairs that overflowed
__device__ float g_h1[N_NODES * D];

// ---------------- single-pass bucket scatter ----------------
__global__ void zero_kernel(int n) {
    int i = blockIdx.x * blockDim.x + threadIdx.x;
    if (i < n) g_cnt[i] = 0;
    if (i == 0) g_ovf_cnt = 0;
}

__global__ void scatter_kernel(const int* __restrict__ ei, int E, int n) {
    int e = blockIdx.x * blockDim.x + threadIdx.x;
    if (e < E) {
        int s = ei[e];       // src row
        int d = ei[E + e];   // dst row
        if (s >= 0 && s < n && d >= 0 && d < n) {
            int p = atomicAdd(&g_cnt[d], 1);
            if (p < CAP) {
                g_bucket[d * CAP + p] = s;
            } else {
                int q = atomicAdd(&g_ovf_cnt, 1);
                if (q < OVF_MAX) { g_ovf[2 * q] = s; g_ovf[2 * q + 1] = d; }
            }
        }
    }
}

// ---------------- fused layer: out = elu(mean_nbr(X)@Wl + X@Wr + b) ----------------
// Phase A: warp-per-4-nodes gather+mean into smem As, stage X rows into Xs.
// Phase B: 16x128 GEMM over K=256 ([As | Xs] @ [Wl ; Wr]) + bias + ELU.
__global__ void __launch_bounds__(NTHREADS)
fused_layer_kernel(const float* __restrict__ Xin, bool use_h1_in,
                   const float* __restrict__ Wl,   // [128,128]
                   const float* __restrict__ Wr,   // [128,128]
                   const float* __restrict__ bias, // [128]
                   float* __restrict__ Out, bool write_h1,
                   int n)
{
    const float* __restrict__ X = use_h1_in ? (const float*)g_h1 : Xin;
    float* __restrict__ out     = write_h1  ? (float*)g_h1 : Out;

    __shared__ float As[TILE * D];   // 8 KB  aggregated means
    __shared__ float Xs[TILE * D];   // 8 KB  self features
    __shared__ float Bs[32 * D];     // 16 KB W k-chunk

    int tid  = threadIdx.x;
    int warp = tid >> 5;             // 0..3
    int lane = tid & 31;
    int row0 = blockIdx.x * TILE;

    // ---------- Phase A: gather (4 nodes per warp) ----------
    #pragma unroll
    for (int t = 0; t < 4; t++) {
        int rt   = (warp << 2) + t;      // row in tile 0..15
        int node = row0 + rt;
        if (node < n) {
            int cnt = g_cnt[node];
            int e = cnt < CAP ? cnt : CAP;
            const int* __restrict__ bk = g_bucket + node * CAP;

            float ax = 0.f, ay = 0.f, az = 0.f, aw = 0.f;
            int i = 0;
            for (; i + 8 <= e; i += 8) {
                int j0 = bk[i + 0]; int j1 = bk[i + 1];
                int j2 = bk[i + 2]; int j3 = bk[i + 3];
                int j4 = bk[i + 4]; int j5 = bk[i + 5];
                int j6 = bk[i + 6]; int j7 = bk[i + 7];
                float4 v0 = *(const float4*)(X + (long long)j0 * D + lane * 4);
                float4 v1 = *(const float4*)(X + (long long)j1 * D + lane * 4);
                float4 v2 = *(const float4*)(X + (long long)j2 * D + lane * 4);
                float4 v3 = *(const float4*)(X + (long long)j3 * D + lane * 4);
                float4 v4 = *(const float4*)(X + (long long)j4 * D + lane * 4);
                float4 v5 = *(const float4*)(X + (long long)j5 * D + lane * 4);
                float4 v6 = *(const float4*)(X + (long long)j6 * D + lane * 4);
                float4 v7 = *(const float4*)(X + (long long)j7 * D + lane * 4);
                ax += (v0.x + v1.x) + (v2.x + v3.x) + ((v4.x + v5.x) + (v6.x + v7.x));
                ay += (v0.y + v1.y) + (v2.y + v3.y) + ((v4.y + v5.y) + (v6.y + v7.y));
                az += (v0.z + v1.z) + (v2.z + v3.z) + ((v4.z + v5.z) + (v6.z + v7.z));
                aw += (v0.w + v1.w) + (v2.w + v3.w) + ((v4.w + v5.w) + (v6.w + v7.w));
            }
            for (; i < e; i++) {
                int j = bk[i];
                float4 v = *(const float4*)(X + (long long)j * D + lane * 4);
                ax += v.x; ay += v.y; az += v.z; aw += v.w;
            }
            // overflow edges (expected none)
            int novf = g_ovf_cnt;
            if (novf > 0) {
                if (novf > OVF_MAX) novf = OVF_MAX;
                for (int q = 0; q < novf; q++) {
                    if (g_ovf[2 * q + 1] == node) {
                        int j = g_ovf[2 * q];
                        float4 v = *(const float4*)(X + (long long)j * D + lane * 4);
                        ax += v.x; ay += v.y; az += v.z; aw += v.w;
                    }
                }
            }
            float inv = 1.0f / (float)(cnt > 0 ? cnt : 1);
            float4 m; m.x = ax * inv; m.y = ay * inv; m.z = az * inv; m.w = aw * inv;
            *(float4*)(As + rt * D + lane * 4) = m;
            *(float4*)(Xs + rt * D + lane * 4) =
                *(const float4*)(X + (long long)node * D + lane * 4);
        } else {
            float4 z = make_float4(0.f, 0.f, 0.f, 0.f);
            *(float4*)(As + rt * D + lane * 4) = z;
            *(float4*)(Xs + rt * D + lane * 4) = z;
        }
    }
    __syncthreads();

    // ---------- Phase B: GEMM 16x128, K = 2*128 ----------
    int tx = tid & 31;   // col group: cols tx*4 .. tx*4+3
    int ty = tid >> 5;   // 0..3: rows ty + 4*r, r in 0..3

    float acc[4][4];
    #pragma unroll
    for (int r = 0; r < 4; r++)
        #pragma unroll
        for (int c = 0; c < 4; c++) acc[r][c] = 0.f;

    #pragma unroll
    for (int phase = 0; phase < 2; phase++) {
        const float* __restrict__ Ap = phase ? Xs : As;   // smem
        const float* __restrict__ Wp = phase ? Wr : Wl;   // gmem (L2)
        #pragma unroll
        for (int k0 = 0; k0 < D; k0 += 32) {
            // W chunk: 32x128 floats = 1024 float4, 8 per thread
            #pragma unroll
            for (int l = 0; l < 8; l++) {
                int idx = tid + l * NTHREADS;   // 0..1023
                int r   = idx >> 5;             // k row 0..31
                int c4  = idx & 31;
                *(float4*)(Bs + r * D + c4 * 4) =
                    *(const float4*)(Wp + (long long)(k0 + r) * D + c4 * 4);
            }
            __syncthreads();
            // inner: 4 k-steps at a time; A row values as one broadcast float4
            #pragma unroll
            for (int kk = 0; kk < 32; kk += 4) {
                float4 a0 = *(const float4*)(Ap + (ty + 0) * D + k0 + kk);
                float4 a1 = *(const float4*)(Ap + (ty + 4) * D + k0 + kk);
                float4 a2 = *(const float4*)(Ap + (ty + 8) * D + k0 + kk);
                float4 a3 = *(const float4*)(Ap + (ty + 12) * D + k0 + kk);
                #pragma unroll
                for (int j = 0; j < 4; j++) {
                    float4 bv = *(const float4*)(Bs + (kk + j) * D + tx * 4);
                    float e0 = j == 0 ? a0.x : j == 1 ? a0.y : j == 2 ? a0.z : a0.w;
                    float e1 = j == 0 ? a1.x : j == 1 ? a1.y : j == 2 ? a1.z : a1.w;
                    float e2 = j == 0 ? a2.x : j == 1 ? a2.y : j == 2 ? a2.z : a2.w;
                    float e3 = j == 0 ? a3.x : j == 1 ? a3.y : j == 2 ? a3.z : a3.w;
                    acc[0][0] += e0 * bv.x; acc[0][1] += e0 * bv.y;
                    acc[0][2] += e0 * bv.z; acc[0][3] += e0 * bv.w;
                    acc[1][0] += e1 * bv.x; acc[1][1] += e1 * bv.y;
                    acc[1][2] += e1 * bv.z; acc[1][3] += e1 * bv.w;
                    acc[2][0] += e2 * bv.x; acc[2][1] += e2 * bv.y;
                    acc[2][2] += e2 * bv.z; acc[2][3] += e2 * bv.w;
                    acc[3][0] += e3 * bv.x; acc[3][1] += e3 * bv.y;
                    acc[3][2] += e3 * bv.z; acc[3][3] += e3 * bv.w;
                }
            }
            __syncthreads();
        }
    }

    // ---------- epilogue ----------
    float4 bv = *(const float4*)(bias + tx * 4);
    #pragma unroll
    for (int r = 0; r < 4; r++) {
        int gr = row0 + ty + r * 4;
        if (gr < n) {
            float4 o;
            o.x = acc[r][0] + bv.x;
            o.y = acc[r][1] + bv.y;
            o.z = acc[r][2] + bv.z;
            o.w = acc[r][3] + bv.w;
            o.x = o.x > 0.f ? o.x : (__expf(o.x) - 1.0f);
            o.y = o.y > 0.f ? o.y : (__expf(o.y) - 1.0f);
            o.z = o.z > 0.f ? o.z : (__expf(o.z) - 1.0f);
            o.w = o.w > 0.f ? o.w : (__expf(o.w) - 1.0f);
            *(float4*)(out + (long long)gr * D + tx * 4) = o;
        }
    }
}

// ---------------- launch ----------------
extern "C" void kernel_launch(void* const* d_in, const int* in_sizes, int n_in,
                              void* d_out, int out_size) {
    const float* x   = (const float*)d_in[0];
    const int*   ei  = (const int*)d_in[1];      // int32 edge_index [2, E]
    const float* Wl0 = (const float*)d_in[2];
    const float* b0  = (const float*)d_in[3];
    const float* Wr0 = (const float*)d_in[4];
    const float* Wl1 = (const float*)d_in[5];
    const float* b1  = (const float*)d_in[6];
    const float* Wr1 = (const float*)d_in[7];
    float*       out = (float*)d_out;

    const int N = in_sizes[0] / D;          // 10000
    const int E = in_sizes[1] / 2;          // 640000

    // single-pass bucket build (rebuilt every launch)
    zero_kernel<<<(N + 255) / 256, 256>>>(N);
    scatter_kernel<<<(E + 255) / 256, 256>>>(ei, E, N);

    const int blocks = (N + TILE - 1) / TILE;   // 625

    // layer 0: fused agg+gemm -> g_h1
    fused_layer_kernel<<<blocks, NTHREADS>>>(x, false, Wl0, Wr0, b0, nullptr, true, N);
    // layer 1: fused agg+gemm -> d_out
    fused_layer_kernel<<<blocks, NTHREADS>>>(nullptr, true, Wl1, Wr1, b1, out, false, N);
}